// round 1
// baseline (speedup 1.0000x reference)
#include <cuda_runtime.h>

// Problem constants
#define B_N   2048
#define C_N   128
#define I_N   16
#define E_N   10
#define KR    276      // 256 (x_l*x_i) + 16 (x_l) + 1 (const) + 3 pad
#define MJN   64       // 4 "m" outputs x 16 j
#define OUTW  512      // 4*C

// Scratch (device globals — allocation-free)
__device__ float g_A[E_N * C_N * KR * MJN];   // ~90.4 MB folded weights, layout [e][c][krow][mjcol]
__device__ int   g_cnt[E_N];
__device__ int   g_list[E_N * B_N];

// ---------------------------------------------------------------------------
__global__ void k_zero() {
    if (threadIdx.x < E_N) g_cnt[threadIdx.x] = 0;
}

// Group nodes by chemical element (y is one-hot)
__global__ void k_group(const float* __restrict__ y) {
    int b = blockIdx.x * blockDim.x + threadIdx.x;
    if (b >= B_N) return;
    int e = 0;
#pragma unroll
    for (int q = 0; q < E_N; q++)
        if (y[b * E_N + q] > 0.5f) e = q;
    int pos = atomicAdd(&g_cnt[e], 1);
    g_list[e * B_N + pos] = b;
}

// ---------------------------------------------------------------------------
// Fold element weights into U tensors:
//   g_A[e][c][l*16+i][m*16+j]  = sum_k U3[m,i,j,l,k] * W3[e,k,c]
//   g_A[e][c][256+l][m*16+j]   = sum_k U2[m,j,l,k]   * W2[e,k,c]
//   g_A[e][c][272][m*16+j]     = sum_k U1[m,j,k]     * W1[e,k,c]
//   rows 273..275 = 0 (padding)
// m columns: 0 = irrep0 (m=0), 1..3 = irrep1 (m=0..2)
__global__ void __launch_bounds__(256) k_prep(
    const float* __restrict__ U3_0, const float* __restrict__ U2_0, const float* __restrict__ U1_0,
    const float* __restrict__ W3_0, const float* __restrict__ W2_0, const float* __restrict__ W1_0,
    const float* __restrict__ U3_1, const float* __restrict__ U2_1, const float* __restrict__ U1_1,
    const float* __restrict__ W3_1, const float* __restrict__ W2_1, const float* __restrict__ W1_1)
{
    __shared__ float u0s[368];    // irrep0 U slice for this krow
    __shared__ float u1s[1584];   // irrep1 U slice for this krow
    const int krow = blockIdx.x;
    const int tid  = threadIdx.x;

    if (krow < 256) {
        const int l = krow >> 4, i = krow & 15;
        for (int idx = tid; idx < 16 * 23; idx += 256) {
            int j = idx / 23, k = idx - j * 23;
            u0s[idx] = U3_0[((i * 16 + j) * 16 + l) * 23 + k];
        }
        for (int idx = tid; idx < 3 * 16 * 33; idx += 256) {
            int m = idx / 528, r = idx - m * 528;
            int j = r / 33, k = r - j * 33;
            u1s[idx] = U3_1[(((m * 16 + i) * 16 + j) * 16 + l) * 33 + k];
        }
    } else if (krow < 272) {
        const int l = krow - 256;
        for (int idx = tid; idx < 16 * 4; idx += 256) {
            int j = idx >> 2, k = idx & 3;
            u0s[idx] = U2_0[(j * 16 + l) * 4 + k];
        }
        for (int idx = tid; idx < 3 * 16 * 5; idx += 256) {
            int m = idx / 80, r = idx - m * 80;
            int j = r / 5, k = r - j * 5;
            u1s[idx] = U2_1[((m * 16 + j) * 16 + l) * 5 + k];
        }
    } else if (krow == 272) {
        if (tid < 16) u0s[tid] = U1_0[tid];
        if (tid < 48) u1s[tid] = U1_1[tid];
    }
    __syncthreads();

    for (int ec = tid; ec < E_N * C_N; ec += 256) {
        const int e = ec >> 7, c = ec & 127;
        float* outp = &g_A[(ec * KR + krow) * MJN];

        if (krow >= 273) {
            for (int col = 0; col < MJN; col++) outp[col] = 0.f;
        } else if (krow < 256) {
            float w[33];
#pragma unroll
            for (int k = 0; k < 23; k++) w[k] = W3_0[(e * 23 + k) * 128 + c];
#pragma unroll
            for (int j = 0; j < 16; j++) {
                float a = 0.f;
#pragma unroll
                for (int k = 0; k < 23; k++) a += u0s[j * 23 + k] * w[k];
                outp[j] = a;
            }
#pragma unroll
            for (int k = 0; k < 33; k++) w[k] = W3_1[(e * 33 + k) * 128 + c];
            for (int m = 0; m < 3; m++) {
#pragma unroll
                for (int j = 0; j < 16; j++) {
                    float a = 0.f;
#pragma unroll
                    for (int k = 0; k < 33; k++) a += u1s[(m * 16 + j) * 33 + k] * w[k];
                    outp[16 + m * 16 + j] = a;
                }
            }
        } else if (krow < 272) {
            float w[5];
#pragma unroll
            for (int k = 0; k < 4; k++) w[k] = W2_0[(e * 4 + k) * 128 + c];
#pragma unroll
            for (int j = 0; j < 16; j++) {
                float a = 0.f;
#pragma unroll
                for (int k = 0; k < 4; k++) a += u0s[j * 4 + k] * w[k];
                outp[j] = a;
            }
#pragma unroll
            for (int k = 0; k < 5; k++) w[k] = W2_1[(e * 5 + k) * 128 + c];
            for (int m = 0; m < 3; m++) {
#pragma unroll
                for (int j = 0; j < 16; j++) {
                    float a = 0.f;
#pragma unroll
                    for (int k = 0; k < 5; k++) a += u1s[(m * 16 + j) * 5 + k] * w[k];
                    outp[16 + m * 16 + j] = a;
                }
            }
        } else {  // krow == 272
            const float w0 = W1_0[e * 128 + c];
#pragma unroll
            for (int j = 0; j < 16; j++) outp[j] = u0s[j] * w0;
            const float w1 = W1_1[e * 128 + c];
#pragma unroll
            for (int mj = 0; mj < 48; mj++) outp[16 + mj] = u1s[mj] * w1;
        }
    }
}

// ---------------------------------------------------------------------------
// Main: per (e,c) CTA. A[276][64] resident in smem; loop node-tiles of 64.
// B[276][64] built on the fly: rows 0..255 = x_l*x_i ; 256..271 = x_l ; 272 = 1.
// SGEMM 64(mj) x 64(n) with 8x4 thread tiles, then 16-term epilogue.
__global__ void __launch_bounds__(128) k_main(const float* __restrict__ x,
                                              float* __restrict__ out)
{
    extern __shared__ float sm[];
    float* As = sm;               // KR*64 = 17664 floats
    float* Bs = sm + KR * MJN;    // KR*64

    const int c = blockIdx.x, e = blockIdx.y;
    const int tid = threadIdx.x;

    // Load folded A tile (coalesced float4)
    {
        const float4* gsrc = (const float4*)&g_A[(e * C_N + c) * KR * MJN];
        float4* dst = (float4*)As;
        for (int idx = tid; idx < KR * MJN / 4; idx += 128) dst[idx] = gsrc[idx];
    }

    const int cnt = g_cnt[e];
    const int* lst = &g_list[e * B_N];
    const int ntiles = (cnt + 63) >> 6;

    const int ty = tid >> 4;   // 0..7  (mj rows, x8)
    const int tx = tid & 15;   // 0..15 (n cols, x4)

    for (int t = 0; t < ntiles; t++) {
        __syncthreads();  // A ready / previous tile fully consumed

        // --- build B tile ---
        {
            const int n = tid & 63, grp = tid >> 6;   // grp 0: k 0..137, grp 1: k 138..275
            const int idx = t * 64 + n;
            const bool valid = idx < cnt;
            float xr[16];
            if (valid) {
                const float4* xp = (const float4*)&x[(lst[idx] * C_N + c) * I_N];
                float4 v0 = xp[0], v1 = xp[1], v2 = xp[2], v3 = xp[3];
                xr[0] = v0.x; xr[1] = v0.y; xr[2]  = v0.z; xr[3]  = v0.w;
                xr[4] = v1.x; xr[5] = v1.y; xr[6]  = v1.z; xr[7]  = v1.w;
                xr[8] = v2.x; xr[9] = v2.y; xr[10] = v2.z; xr[11] = v2.w;
                xr[12]= v3.x; xr[13]= v3.y; xr[14] = v3.z; xr[15] = v3.w;
            } else {
#pragma unroll
                for (int q = 0; q < 16; q++) xr[q] = 0.f;
            }
            const int k0 = grp * 138, k1 = k0 + 138;
            for (int k = k0; k < k1; k++) {
                float v;
                if (k < 256)       v = xr[k >> 4] * xr[k & 15];
                else if (k < 272)  v = xr[k - 256];
                else if (k == 272) v = valid ? 1.f : 0.f;
                else               v = 0.f;
                Bs[k * 64 + n] = v;
            }
        }
        __syncthreads();

        // --- main matmul: out4[64 x 64] ---
        float acc[8][4];
#pragma unroll
        for (int r = 0; r < 8; r++)
#pragma unroll
            for (int q = 0; q < 4; q++) acc[r][q] = 0.f;

        const float* Ab = As + ty * 8;
        const float* Bb = Bs + tx * 4;
#pragma unroll 4
        for (int k = 0; k < KR; k++) {
            float4 a0 = *(const float4*)(Ab + k * 64);
            float4 a1 = *(const float4*)(Ab + k * 64 + 4);
            float4 bq = *(const float4*)(Bb + k * 64);
            float ar[8] = {a0.x, a0.y, a0.z, a0.w, a1.x, a1.y, a1.z, a1.w};
            float br[4] = {bq.x, bq.y, bq.z, bq.w};
#pragma unroll
            for (int r = 0; r < 8; r++)
#pragma unroll
                for (int q = 0; q < 4; q++) acc[r][q] += ar[r] * br[q];
        }
        __syncthreads();  // all Bs reads done before overwriting rows 0..63 with C

        // --- stash out4 into Bs rows 0..63 (x rows 256..271 stay intact) ---
#pragma unroll
        for (int r = 0; r < 8; r++) {
            *(float4*)(Bs + (ty * 8 + r) * 64 + tx * 4) =
                make_float4(acc[r][0], acc[r][1], acc[r][2], acc[r][3]);
        }
        __syncthreads();

        // --- epilogue: out[m] = sum_j out4[m,j] * x_j ---
        for (int p = tid; p < 256; p += 128) {
            const int m = p >> 6, n = p & 63;
            const int idx = t * 64 + n;
            if (idx < cnt) {
                float s = 0.f;
#pragma unroll
                for (int j = 0; j < 16; j++)
                    s += Bs[(m * 16 + j) * 64 + n] * Bs[(256 + j) * 64 + n];
                const int b = lst[idx];
                const int col = (m == 0) ? c : (128 + c * 3 + (m - 1));
                out[b * OUTW + col] = s;
            }
        }
    }
}

// ---------------------------------------------------------------------------
extern "C" void kernel_launch(void* const* d_in, const int* in_sizes, int n_in,
                              void* d_out, int out_size)
{
    (void)in_sizes; (void)n_in; (void)out_size;
    const float* x    = (const float*)d_in[0];
    const float* y    = (const float*)d_in[1];
    const float* U3_0 = (const float*)d_in[2];
    const float* U2_0 = (const float*)d_in[3];
    const float* U1_0 = (const float*)d_in[4];
    const float* W3_0 = (const float*)d_in[5];
    const float* W2_0 = (const float*)d_in[6];
    const float* W1_0 = (const float*)d_in[7];
    const float* U3_1 = (const float*)d_in[8];
    const float* U2_1 = (const float*)d_in[9];
    const float* U1_1 = (const float*)d_in[10];
    const float* W3_1 = (const float*)d_in[11];
    const float* W2_1 = (const float*)d_in[12];
    const float* W1_1 = (const float*)d_in[13];

    const int smem_main = 2 * KR * MJN * (int)sizeof(float);  // 141312 B
    cudaFuncSetAttribute(k_main, cudaFuncAttributeMaxDynamicSharedMemorySize, smem_main);

    k_zero<<<1, 32>>>();
    k_group<<<(B_N + 255) / 256, 256>>>(y);
    k_prep<<<KR, 256>>>(U3_0, U2_0, U1_0, W3_0, W2_0, W1_0,
                        U3_1, U2_1, U1_1, W3_1, W2_1, W1_1);
    k_main<<<dim3(C_N, E_N), 128, smem_main>>>(x, (float*)d_out);
}

// round 2
// speedup vs baseline: 1.1156x; 1.1156x over previous
#include <cuda_runtime.h>
#include <cstdint>

// Problem constants
#define B_N   2048
#define C_N   128
#define I_N   16
#define E_N   10
#define KR    276      // logical k rows: 256 (x_l*x_i) + 16 (x_l) + 1 (const) + 3 pad(zeroed by prep)
#define KP    280      // padded to multiple of 8 for mma k-steps
#define AST   72       // smem row stride (bank-conflict-free fragment loads)
#define MJN   64       // 4 "m" outputs x 16 j
#define OUTW  512      // 4*C

// Scratch (device globals — allocation-free)
__device__ float g_A[E_N * C_N * KR * MJN];   // folded weights [e][c][krow][mjcol]
__device__ int   g_cnt[E_N];
__device__ int   g_list[E_N * B_N];

// ---------------------------------------------------------------------------
__global__ void k_zero() {
    if (threadIdx.x < E_N) g_cnt[threadIdx.x] = 0;
}

__global__ void k_group(const float* __restrict__ y) {
    int b = blockIdx.x * blockDim.x + threadIdx.x;
    if (b >= B_N) return;
    int e = 0;
#pragma unroll
    for (int q = 0; q < E_N; q++)
        if (y[b * E_N + q] > 0.5f) e = q;
    int pos = atomicAdd(&g_cnt[e], 1);
    g_list[e * B_N + pos] = b;
}

// ---------------------------------------------------------------------------
// Fold element weights into U tensors (unchanged from R1):
//   g_A[e][c][l*16+i][m*16+j]  = sum_k U3[m,i,j,l,k] * W3[e,k,c]
//   g_A[e][c][256+l][m*16+j]   = sum_k U2[m,j,l,k]   * W2[e,k,c]
//   g_A[e][c][272][m*16+j]     = sum_k U1[m,j,k]     * W1[e,k,c]
//   rows 273..275 = 0
__global__ void __launch_bounds__(256) k_prep(
    const float* __restrict__ U3_0, const float* __restrict__ U2_0, const float* __restrict__ U1_0,
    const float* __restrict__ W3_0, const float* __restrict__ W2_0, const float* __restrict__ W1_0,
    const float* __restrict__ U3_1, const float* __restrict__ U2_1, const float* __restrict__ U1_1,
    const float* __restrict__ W3_1, const float* __restrict__ W2_1, const float* __restrict__ W1_1)
{
    __shared__ float u0s[368];
    __shared__ float u1s[1584];
    const int krow = blockIdx.x;
    const int tid  = threadIdx.x;

    if (krow < 256) {
        const int l = krow >> 4, i = krow & 15;
        for (int idx = tid; idx < 16 * 23; idx += 256) {
            int j = idx / 23, k = idx - j * 23;
            u0s[idx] = U3_0[((i * 16 + j) * 16 + l) * 23 + k];
        }
        for (int idx = tid; idx < 3 * 16 * 33; idx += 256) {
            int m = idx / 528, r = idx - m * 528;
            int j = r / 33, k = r - j * 33;
            u1s[idx] = U3_1[(((m * 16 + i) * 16 + j) * 16 + l) * 33 + k];
        }
    } else if (krow < 272) {
        const int l = krow - 256;
        for (int idx = tid; idx < 16 * 4; idx += 256) {
            int j = idx >> 2, k = idx & 3;
            u0s[idx] = U2_0[(j * 16 + l) * 4 + k];
        }
        for (int idx = tid; idx < 3 * 16 * 5; idx += 256) {
            int m = idx / 80, r = idx - m * 80;
            int j = r / 5, k = r - j * 5;
            u1s[idx] = U2_1[((m * 16 + j) * 16 + l) * 5 + k];
        }
    } else if (krow == 272) {
        if (tid < 16) u0s[tid] = U1_0[tid];
        if (tid < 48) u1s[tid] = U1_1[tid];
    }
    __syncthreads();

    for (int ec = tid; ec < E_N * C_N; ec += 256) {
        const int e = ec >> 7, c = ec & 127;
        float* outp = &g_A[(ec * KR + krow) * MJN];

        if (krow >= 273) {
            for (int col = 0; col < MJN; col++) outp[col] = 0.f;
        } else if (krow < 256) {
            float w[33];
#pragma unroll
            for (int k = 0; k < 23; k++) w[k] = W3_0[(e * 23 + k) * 128 + c];
#pragma unroll
            for (int j = 0; j < 16; j++) {
                float a = 0.f;
#pragma unroll
                for (int k = 0; k < 23; k++) a += u0s[j * 23 + k] * w[k];
                outp[j] = a;
            }
#pragma unroll
            for (int k = 0; k < 33; k++) w[k] = W3_1[(e * 33 + k) * 128 + c];
            for (int m = 0; m < 3; m++) {
#pragma unroll
                for (int j = 0; j < 16; j++) {
                    float a = 0.f;
#pragma unroll
                    for (int k = 0; k < 33; k++) a += u1s[(m * 16 + j) * 33 + k] * w[k];
                    outp[16 + m * 16 + j] = a;
                }
            }
        } else if (krow < 272) {
            float w[5];
#pragma unroll
            for (int k = 0; k < 4; k++) w[k] = W2_0[(e * 4 + k) * 128 + c];
#pragma unroll
            for (int j = 0; j < 16; j++) {
                float a = 0.f;
#pragma unroll
                for (int k = 0; k < 4; k++) a += u0s[j * 4 + k] * w[k];
                outp[j] = a;
            }
#pragma unroll
            for (int k = 0; k < 5; k++) w[k] = W2_1[(e * 5 + k) * 128 + c];
            for (int m = 0; m < 3; m++) {
#pragma unroll
                for (int j = 0; j < 16; j++) {
                    float a = 0.f;
#pragma unroll
                    for (int k = 0; k < 5; k++) a += u1s[(m * 16 + j) * 5 + k] * w[k];
                    outp[16 + m * 16 + j] = a;
                }
            }
        } else {  // krow == 272
            const float w0 = W1_0[e * 128 + c];
#pragma unroll
            for (int j = 0; j < 16; j++) outp[j] = u0s[j] * w0;
            const float w1 = W1_1[e * 128 + c];
#pragma unroll
            for (int mj = 0; mj < 48; mj++) outp[16 + mj] = u1s[mj] * w1;
        }
    }
}

// ---------------------------------------------------------------------------
// Split-tf32 helpers
__device__ __forceinline__ void split_tf32(float v, uint32_t& hi, uint32_t& lo) {
    float h, l;
    asm("cvt.rna.tf32.f32 %0, %1;" : "=f"(h) : "f"(v));
    float r = v - h;
    asm("cvt.rna.tf32.f32 %0, %1;" : "=f"(l) : "f"(r));
    hi = __float_as_uint(h);
    lo = __float_as_uint(l);
}

__device__ __forceinline__ void mma_tf32(float d[4],
                                         uint32_t a0, uint32_t a1, uint32_t a2, uint32_t a3,
                                         uint32_t b0, uint32_t b1) {
    asm volatile(
        "mma.sync.aligned.m16n8k8.row.col.f32.tf32.tf32.f32 "
        "{%0,%1,%2,%3}, {%4,%5,%6,%7}, {%8,%9}, {%0,%1,%2,%3};"
        : "+f"(d[0]), "+f"(d[1]), "+f"(d[2]), "+f"(d[3])
        : "r"(a0), "r"(a1), "r"(a2), "r"(a3), "r"(b0), "r"(b1));
}

// ---------------------------------------------------------------------------
// Main: per (e,c) CTA, 256 threads, tensor-core 64x64x280 GEMM per node tile,
// split-tf32 (hh + hl + lh) for ~1e-5 accuracy, then 16-term epilogue.
__global__ void __launch_bounds__(256) k_main(const float* __restrict__ x,
                                              float* __restrict__ out)
{
    extern __shared__ float sm[];
    float* As = sm;                    // KP * AST
    float* Bs = sm + KP * AST;         // KP * AST
    float* Cs = sm + 2 * KP * AST;     // 64 * AST

    const int c = blockIdx.x, e = blockIdx.y;
    const int tid  = threadIdx.x;
    const int lane = tid & 31, warp = tid >> 5;
    const int gid  = lane >> 2, tig = lane & 3;
    const int m_base = (warp & 3) * 16;    // 4 m-tiles of 16
    const int n_base = (warp >> 2) * 32;   // 2 n-halves of 32

    // Load folded A (276x64) into As[k*AST + mj]; zero pad rows 276..279
    {
        const float4* src = (const float4*)&g_A[(e * C_N + c) * KR * MJN];
        for (int idx = tid; idx < KR * MJN / 4; idx += 256) {
            int k = idx >> 4;          // 16 float4 per 64-col row
            int m4 = (idx & 15) << 2;
            *(float4*)&As[k * AST + m4] = src[idx];
        }
        for (int idx = tid; idx < 4 * MJN; idx += 256)
            As[(KR + 3 + (idx >> 6)) * AST + (idx & 63)] = 0.f;  // rows 279? see below
        // note: rows 276..279 zeroed: (idx>>6) in 0..3 -> rows 279? fix: base row 276
    }
    // correct zeroing of rows 276..279 (the loop above used KR+3=279 base by mistake-proofing: redo cleanly)
    for (int idx = tid; idx < 4 * MJN; idx += 256)
        As[(276 + (idx >> 6)) * AST + (idx & 63)] = 0.f;

    const int cnt = g_cnt[e];
    const int* lst = &g_list[e * B_N];
    const int ntiles = (cnt + 63) >> 6;

    for (int t = 0; t < ntiles; t++) {
        __syncthreads();   // A ready / previous epilogue done with Bs & Cs

        // --- build B tile: Bs[k*AST + n], rows 0..279 ---
        {
            const int n = tid & 63, grp = tid >> 6;   // 4 groups x 70 rows
            const int idx = t * 64 + n;
            const bool valid = idx < cnt;
            float xr[16];
            if (valid) {
                const float4* xp = (const float4*)&x[(lst[idx] * C_N + c) * I_N];
                float4 v0 = xp[0], v1 = xp[1], v2 = xp[2], v3 = xp[3];
                xr[0] = v0.x; xr[1] = v0.y; xr[2]  = v0.z; xr[3]  = v0.w;
                xr[4] = v1.x; xr[5] = v1.y; xr[6]  = v1.z; xr[7]  = v1.w;
                xr[8] = v2.x; xr[9] = v2.y; xr[10] = v2.z; xr[11] = v2.w;
                xr[12]= v3.x; xr[13]= v3.y; xr[14] = v3.z; xr[15] = v3.w;
            } else {
#pragma unroll
                for (int q = 0; q < 16; q++) xr[q] = 0.f;
            }
            const int k0 = grp * 70, k1 = k0 + 70;
            for (int k = k0; k < k1; k++) {
                float v = 0.f;
                if (valid) {
                    if (k < 256)       v = xr[k >> 4] * xr[k & 15];
                    else if (k < 272)  v = xr[k - 256];
                    else if (k == 272) v = 1.f;
                }
                Bs[k * AST + n] = v;
            }
        }
        __syncthreads();

        // --- tensor-core GEMM: out4[64 x 64] = A[64 x 280] * B[280 x 64] ---
        float d[4][4];
#pragma unroll
        for (int nf = 0; nf < 4; nf++)
#pragma unroll
            for (int q = 0; q < 4; q++) d[nf][q] = 0.f;

#pragma unroll 1
        for (int ks = 0; ks < KP / 8; ks++) {
            const int k0 = ks * 8;
            // A fragment (m16 x k8), split hi/lo
            float a0 = As[(k0 + tig)     * AST + m_base + gid];
            float a1 = As[(k0 + tig)     * AST + m_base + 8 + gid];
            float a2 = As[(k0 + tig + 4) * AST + m_base + gid];
            float a3 = As[(k0 + tig + 4) * AST + m_base + 8 + gid];
            uint32_t ah[4], al[4];
            split_tf32(a0, ah[0], al[0]);
            split_tf32(a1, ah[1], al[1]);
            split_tf32(a2, ah[2], al[2]);
            split_tf32(a3, ah[3], al[3]);
#pragma unroll
            for (int nf = 0; nf < 4; nf++) {
                float b0 = Bs[(k0 + tig)     * AST + n_base + nf * 8 + gid];
                float b1 = Bs[(k0 + tig + 4) * AST + n_base + nf * 8 + gid];
                uint32_t bh0, bl0, bh1, bl1;
                split_tf32(b0, bh0, bl0);
                split_tf32(b1, bh1, bl1);
                mma_tf32(d[nf], ah[0], ah[1], ah[2], ah[3], bh0, bh1);  // hh
                mma_tf32(d[nf], ah[0], ah[1], ah[2], ah[3], bl0, bl1);  // hl
                mma_tf32(d[nf], al[0], al[1], al[2], al[3], bh0, bh1);  // lh
            }
        }

        // --- store out4 to Cs[mj * AST + n] ---
#pragma unroll
        for (int nf = 0; nf < 4; nf++) {
            const int nn = n_base + nf * 8 + tig * 2;
            *(float2*)&Cs[(m_base + gid)     * AST + nn] = make_float2(d[nf][0], d[nf][1]);
            *(float2*)&Cs[(m_base + 8 + gid) * AST + nn] = make_float2(d[nf][2], d[nf][3]);
        }
        __syncthreads();

        // --- epilogue: out[m,n] = sum_j out4[m*16+j, n] * x_j[n] ---
        {
            const int m = tid >> 6, n = tid & 63;
            const int idx = t * 64 + n;
            if (idx < cnt) {
                float s = 0.f;
#pragma unroll
                for (int j = 0; j < 16; j++)
                    s += Cs[(m * 16 + j) * AST + n] * Bs[(256 + j) * AST + n];
                const int b = lst[idx];
                const int col = (m == 0) ? c : (128 + c * 3 + (m - 1));
                out[b * OUTW + col] = s;
            }
        }
    }
}

// ---------------------------------------------------------------------------
extern "C" void kernel_launch(void* const* d_in, const int* in_sizes, int n_in,
                              void* d_out, int out_size)
{
    (void)in_sizes; (void)n_in; (void)out_size;
    const float* x    = (const float*)d_in[0];
    const float* y    = (const float*)d_in[1];
    const float* U3_0 = (const float*)d_in[2];
    const float* U2_0 = (const float*)d_in[3];
    const float* U1_0 = (const float*)d_in[4];
    const float* W3_0 = (const float*)d_in[5];
    const float* W2_0 = (const float*)d_in[6];
    const float* W1_0 = (const float*)d_in[7];
    const float* U3_1 = (const float*)d_in[8];
    const float* U2_1 = (const float*)d_in[9];
    const float* U1_1 = (const float*)d_in[10];
    const float* W3_1 = (const float*)d_in[11];
    const float* W2_1 = (const float*)d_in[12];
    const float* W1_1 = (const float*)d_in[13];

    const int smem_main = (2 * KP * AST + 64 * AST) * (int)sizeof(float);  // 179,712 B
    cudaFuncSetAttribute(k_main, cudaFuncAttributeMaxDynamicSharedMemorySize, smem_main);

    k_zero<<<1, 32>>>();
    k_group<<<(B_N + 255) / 256, 256>>>(y);
    k_prep<<<KR, 256>>>(U3_0, U2_0, U1_0, W3_0, W2_0, W1_0,
                        U3_1, U2_1, U1_1, W3_1, W2_1, W1_1);
    k_main<<<dim3(C_N, E_N), 256, smem_main>>>(x, (float*)d_out);
}

// round 3
// speedup vs baseline: 2.1638x; 1.9396x over previous
#include <cuda_runtime.h>
#include <cuda_bf16.h>
#include <cstdint>

// Problem constants
#define B_N   2048
#define C_N   128
#define I_N   16
#define E_N   10
#define KPRE  138      // k-pair rows written by prep (276 krows)
#define KP2   144      // padded k-pair rows in k_main (288 k = 18 * k16)
#define AST   72       // smem row stride (==8 mod 32 -> conflict-free frags)
#define MJN   64       // 4 "m" outputs x 16 j
#define OUTW  512      // 4*C

// Scratch (device globals — allocation-free)
// Split-bf16 folded weights, k-pair packed: word[(ec*138+kp)*64+mj]
//   low16 = bf16 of krow 2kp, high16 = bf16 of krow 2kp+1
__device__ __align__(16) uint32_t g_Ah[(size_t)E_N * C_N * KPRE * MJN];
__device__ __align__(16) uint32_t g_Al[(size_t)E_N * C_N * KPRE * MJN];
__device__ int g_cnt[E_N];
__device__ int g_list[E_N * B_N];

// ---------------------------------------------------------------------------
__global__ void k_zero() {
    if (threadIdx.x < E_N) g_cnt[threadIdx.x] = 0;
}

__global__ void k_group(const float* __restrict__ y) {
    int b = blockIdx.x * blockDim.x + threadIdx.x;
    if (b >= B_N) return;
    int e = 0;
#pragma unroll
    for (int q = 0; q < E_N; q++)
        if (y[b * E_N + q] > 0.5f) e = q;
    int pos = atomicAdd(&g_cnt[e], 1);
    g_list[e * B_N + pos] = b;
}

// ---------------------------------------------------------------------------
// bf16 split helpers: hi = truncate-to-bf16(v), lo = round-to-bf16(v - hi)
__device__ __forceinline__ void split_pack(float v0, float v1,
                                           uint32_t& hiw, uint32_t& low) {
    uint32_t u0 = __float_as_uint(v0), u1 = __float_as_uint(v1);
    hiw = __byte_perm(u0, u1, 0x7632);        // {lo16 = hi-bits of v0, hi16 = of v1}
    float l0 = v0 - __uint_as_float(u0 & 0xffff0000u);
    float l1 = v1 - __uint_as_float(u1 & 0xffff0000u);
    asm("cvt.rn.bf16x2.f32 %0, %1, %2;" : "=r"(low) : "f"(l1), "f"(l0));
}

// ---------------------------------------------------------------------------
// k_prep2: fold element weights into split-bf16 A, one block per k-pair kp.
//   krow<256 (kp<128):  out = sum_k U3[m,i,j,l,k] * W3[e,k,c]   (l=krow>>4,i=krow&15)
//   krow 256..271:      out = sum_k U2[m,j,l,k]   * W2[e,k,c]   (l=krow-256)
//   krow 272:           out = U1[m,j] * W1[e,0,c];  273..275 = 0
// Output m columns: 0 = irrep0, 1..3 = irrep1.
template <int K0, int K1>
__device__ void prep_compute(int kp,
                             const float* __restrict__ W0,
                             const float* __restrict__ W1,
                             const float* __restrict__ us0,
                             const float* __restrict__ us1,
                             float* __restrict__ Os, int tid)
{
    const int ec_l = tid & 31;
    const int slot = tid >> 5;
    const int h    = slot >> 2;    // krow half (0: 2kp, 1: 2kp+1)
    const int mjg  = slot & 3;     // 0: irrep0 (mj 0..15), 1..3: irrep1 rows

    for (int ch = 0; ch < 40; ch++) {
        const int ec = ch * 32 + ec_l;
        const int e = ec >> 7, c = ec & 127;
        float o[16];
#pragma unroll
        for (int q = 0; q < 16; q++) o[q] = 0.f;

        if (mjg == 0) {
#pragma unroll
            for (int k = 0; k < K0; k++) {
                float wk = W0[(e * K0 + k) * 128 + c];
#pragma unroll
                for (int q = 0; q < 8; q++) {
                    float2 u = *(const float2*)&us0[h * 384 + k * 16 + 2 * q];
                    o[2 * q]     += u.x * wk;
                    o[2 * q + 1] += u.y * wk;
                }
            }
        } else {
            const int mb = (mjg - 1) * 16;
#pragma unroll
            for (int k = 0; k < K1; k++) {
                float wk = W1[(e * K1 + k) * 128 + c];
#pragma unroll
                for (int q = 0; q < 8; q++) {
                    float2 u = *(const float2*)&us1[h * 1632 + k * 48 + mb + 2 * q];
                    o[2 * q]     += u.x * wk;
                    o[2 * q + 1] += u.y * wk;
                }
            }
        }
#pragma unroll
        for (int q = 0; q < 8; q++)
            *(float2*)&Os[ec_l * 130 + h * 64 + mjg * 16 + 2 * q] =
                make_float2(o[2 * q], o[2 * q + 1]);
        __syncthreads();

        // coalesced split+pack+store: lanes cover consecutive mj
        for (int widx = tid; widx < 32 * 64; widx += 256) {
            const int el = widx >> 6, mj = widx & 63;
            float o0 = Os[el * 130 + mj];
            float o1 = Os[el * 130 + 64 + mj];
            uint32_t hiw, low;
            split_pack(o0, o1, hiw, low);
            size_t gi = ((size_t)(ch * 32 + el) * KPRE + kp) * 64 + mj;
            g_Ah[gi] = hiw;
            g_Al[gi] = low;
        }
        __syncthreads();
    }
}

__global__ void __launch_bounds__(256) k_prep2(
    const float* __restrict__ U3_0, const float* __restrict__ U2_0, const float* __restrict__ U1_0,
    const float* __restrict__ W3_0, const float* __restrict__ W2_0, const float* __restrict__ W1_0,
    const float* __restrict__ U3_1, const float* __restrict__ U2_1, const float* __restrict__ U1_1,
    const float* __restrict__ W3_1, const float* __restrict__ W2_1, const float* __restrict__ W1_1)
{
    __shared__ float us0[768];     // [2][K0<=24][16]  (k-major, j contiguous)
    __shared__ float us1[3264];    // [2][K1<=34][48]
    __shared__ float Os[32 * 130]; // staged fp32 outputs: [ec_l][h*64+mj]

    const int kp = blockIdx.x;
    const int tid = threadIdx.x;

    if (kp < 128) {
        const int r0 = 2 * kp, l = r0 >> 4, i0 = r0 & 15;
        for (int idx = tid; idx < 2 * 23 * 16; idx += 256) {
            int h = idx / 368, r = idx % 368, k = r / 16, j = r % 16;
            us0[h * 384 + k * 16 + j] = U3_0[(((i0 + h) * 16 + j) * 16 + l) * 23 + k];
        }
        for (int idx = tid; idx < 2 * 33 * 48; idx += 256) {
            int h = idx / 1584, r = idx % 1584, k = r / 48, mj = r % 48;
            int m = mj >> 4, j = mj & 15;
            us1[h * 1632 + k * 48 + mj] =
                U3_1[(((m * 16 + (i0 + h)) * 16 + j) * 16 + l) * 33 + k];
        }
        __syncthreads();
        prep_compute<23, 33>(kp, W3_0, W3_1, us0, us1, Os, tid);
    } else if (kp < 136) {
        const int l0 = 2 * kp - 256;
        for (int idx = tid; idx < 2 * 4 * 16; idx += 256) {
            int h = idx / 64, r = idx % 64, k = r / 16, j = r % 16;
            us0[h * 384 + k * 16 + j] = U2_0[(j * 16 + (l0 + h)) * 4 + k];
        }
        for (int idx = tid; idx < 2 * 5 * 48; idx += 256) {
            int h = idx / 240, r = idx % 240, k = r / 48, mj = r % 48;
            int m = mj >> 4, j = mj & 15;
            us1[h * 1632 + k * 48 + mj] = U2_1[((m * 16 + j) * 16 + (l0 + h)) * 5 + k];
        }
        __syncthreads();
        prep_compute<4, 5>(kp, W2_0, W2_1, us0, us1, Os, tid);
    } else if (kp == 136) {
        for (int idx = tid; idx < 768; idx += 256) us0[idx] = 0.f;
        for (int idx = tid; idx < 3264; idx += 256) us1[idx] = 0.f;
        __syncthreads();
        if (tid < 16) us0[tid] = U1_0[tid];          // h=0, k=0 row
        if (tid < 48) us1[tid] = U1_1[tid];
        __syncthreads();
        prep_compute<1, 1>(kp, W1_0, W1_1, us0, us1, Os, tid);
    } else {  // kp == 137 : krows 274,275 -> zeros
        __syncthreads();
        prep_compute<0, 0>(kp, W1_0, W1_1, us0, us1, Os, tid);
    }
}

// ---------------------------------------------------------------------------
__device__ __forceinline__ void mma_bf16(float* d,
                                         uint32_t a0, uint32_t a1, uint32_t a2, uint32_t a3,
                                         uint32_t b0, uint32_t b1) {
    asm volatile(
        "mma.sync.aligned.m16n8k16.row.col.f32.bf16.bf16.f32 "
        "{%0,%1,%2,%3}, {%4,%5,%6,%7}, {%8,%9}, {%0,%1,%2,%3};"
        : "+f"(d[0]), "+f"(d[1]), "+f"(d[2]), "+f"(d[3])
        : "r"(a0), "r"(a1), "r"(a2), "r"(a3), "r"(b0), "r"(b1));
}

// smem word offsets for k_main
#define AHS 0
#define ALS (KP2 * AST)          // 10368
#define BHS (2 * KP2 * AST)
#define BLS (3 * KP2 * AST)
#define XSO (4 * KP2 * AST)      // 16 x AST floats
#define CSO (4 * KP2 * AST + 16 * AST)
#define SMW (4 * KP2 * AST + 16 * AST + 64 * AST)   // total words = 47232

// k_main: per (c, e) CTA, 256 threads / 8 warps.
// out4[64 x 64] = A[64 x 288] * B[288 x 64] via split-bf16 mma (hh + hl + lh),
// then epilogue out[m,n] = sum_j out4[m*16+j,n] * x_j[n].
__global__ void __launch_bounds__(256) k_main(const float* __restrict__ x,
                                              float* __restrict__ out)
{
    extern __shared__ uint32_t sm[];
    uint32_t* Ah = sm + AHS;
    uint32_t* Al = sm + ALS;
    uint32_t* Bh = sm + BHS;
    uint32_t* Bl = sm + BLS;
    float*    Xs = (float*)(sm + XSO);
    float*    Cs = (float*)(sm + CSO);

    const int c = blockIdx.x, e = blockIdx.y;
    const int tid  = threadIdx.x;
    const int lane = tid & 31, warp = tid >> 5;
    const int gid  = lane >> 2, tig = lane & 3;
    const int m_base = (warp & 3) * 16;
    const int n_base = (warp >> 2) * 32;

    // ---- load pre-split A tile (138 kp rows x 64), zero pad rows 138..143 ----
    {
        const uint4* srcH = (const uint4*)&g_Ah[(size_t)(e * C_N + c) * KPRE * MJN];
        const uint4* srcL = (const uint4*)&g_Al[(size_t)(e * C_N + c) * KPRE * MJN];
        for (int idx = tid; idx < KPRE * 16; idx += 256) {
            int kp = idx >> 4, c4 = (idx & 15) << 2;
            *(uint4*)&Ah[kp * AST + c4] = srcH[idx];
            *(uint4*)&Al[kp * AST + c4] = srcL[idx];
        }
        for (int idx = tid; idx < 6 * MJN; idx += 256) {
            int kp = KPRE + (idx >> 6), col = idx & 63;
            Ah[kp * AST + col] = 0u;
            Al[kp * AST + col] = 0u;
        }
    }

    const int cnt = g_cnt[e];
    const int* lst = &g_list[e * B_N];
    const int ntiles = (cnt + 63) >> 6;

    const int n   = tid & 63;    // build/epilogue column
    const int grp = tid >> 6;    // 4 groups x 36 kp rows

    for (int t = 0; t < ntiles; t++) {
        __syncthreads();   // A ready / previous tile consumed

        // ---- phase 0: grp 0 loads x into Xs (fp32) ----
        if (grp == 0) {
            const int idx = t * 64 + n;
            float4 v0, v1, v2, v3;
            if (idx < cnt) {
                const float4* xp = (const float4*)&x[((size_t)lst[idx] * C_N + c) * I_N];
                v0 = xp[0]; v1 = xp[1]; v2 = xp[2]; v3 = xp[3];
            } else {
                v0 = v1 = v2 = v3 = make_float4(0.f, 0.f, 0.f, 0.f);
            }
            Xs[0*AST+n]=v0.x;  Xs[1*AST+n]=v0.y;  Xs[2*AST+n]=v0.z;  Xs[3*AST+n]=v0.w;
            Xs[4*AST+n]=v1.x;  Xs[5*AST+n]=v1.y;  Xs[6*AST+n]=v1.z;  Xs[7*AST+n]=v1.w;
            Xs[8*AST+n]=v2.x;  Xs[9*AST+n]=v2.y;  Xs[10*AST+n]=v2.z; Xs[11*AST+n]=v2.w;
            Xs[12*AST+n]=v3.x; Xs[13*AST+n]=v3.y; Xs[14*AST+n]=v3.z; Xs[15*AST+n]=v3.w;
        }
        __syncthreads();

        // ---- phase 1: build split B tile (rows kp = grp*36 .. +36) ----
        {
            const bool valid = (t * 64 + n) < cnt;
            const int kp0 = grp * 36;
            for (int q = 0; q < 36; q++) {
                const int kp = kp0 + q, k0 = 2 * kp;
                float v0, v1;
                if (k0 < 256) {
                    float xa  = Xs[(k0 >> 4) * AST + n];
                    float xb0 = Xs[(k0 & 15) * AST + n];
                    float xb1 = Xs[((k0 & 15) + 1) * AST + n];
                    v0 = xa * xb0; v1 = xa * xb1;
                } else if (k0 < 272) {
                    v0 = Xs[(k0 - 256) * AST + n];
                    v1 = Xs[(k0 - 255) * AST + n];
                } else if (k0 == 272) {
                    v0 = valid ? 1.f : 0.f; v1 = 0.f;
                } else {
                    v0 = 0.f; v1 = 0.f;
                }
                uint32_t hiw, low;
                split_pack(v0, v1, hiw, low);
                Bh[kp * AST + n] = hiw;
                Bl[kp * AST + n] = low;
            }
        }
        __syncthreads();

        // ---- tensor GEMM: 18 k16-steps, hh + hl + lh ----
        float d[4][4];
#pragma unroll
        for (int nf = 0; nf < 4; nf++)
#pragma unroll
            for (int q = 0; q < 4; q++) d[nf][q] = 0.f;

#pragma unroll
        for (int ks = 0; ks < KP2 / 8; ks++) {
            const int kb = ks * 8;
            uint32_t ah0 = Ah[(kb + tig) * AST + m_base + gid];
            uint32_t ah1 = Ah[(kb + tig) * AST + m_base + 8 + gid];
            uint32_t ah2 = Ah[(kb + 4 + tig) * AST + m_base + gid];
            uint32_t ah3 = Ah[(kb + 4 + tig) * AST + m_base + 8 + gid];
            uint32_t al0 = Al[(kb + tig) * AST + m_base + gid];
            uint32_t al1 = Al[(kb + tig) * AST + m_base + 8 + gid];
            uint32_t al2 = Al[(kb + 4 + tig) * AST + m_base + gid];
            uint32_t al3 = Al[(kb + 4 + tig) * AST + m_base + 8 + gid];
#pragma unroll
            for (int nf = 0; nf < 4; nf++) {
                const int nn = n_base + nf * 8 + gid;
                uint32_t bh0 = Bh[(kb + tig) * AST + nn];
                uint32_t bh1 = Bh[(kb + 4 + tig) * AST + nn];
                uint32_t bl0 = Bl[(kb + tig) * AST + nn];
                uint32_t bl1 = Bl[(kb + 4 + tig) * AST + nn];
                mma_bf16(d[nf], ah0, ah1, ah2, ah3, bh0, bh1);  // hh
                mma_bf16(d[nf], ah0, ah1, ah2, ah3, bl0, bl1);  // hl
                mma_bf16(d[nf], al0, al1, al2, al3, bh0, bh1);  // lh
            }
        }

        // ---- stash C into Cs ----
#pragma unroll
        for (int nf = 0; nf < 4; nf++) {
            const int nn = n_base + nf * 8 + 2 * tig;
            *(float2*)&Cs[(m_base + gid) * AST + nn]     = make_float2(d[nf][0], d[nf][1]);
            *(float2*)&Cs[(m_base + 8 + gid) * AST + nn] = make_float2(d[nf][2], d[nf][3]);
        }
        __syncthreads();

        // ---- epilogue: out[m,n] = sum_j C[m*16+j,n] * x_j[n] ----
        {
            const int m = tid >> 6;
            const int idx = t * 64 + n;
            if (idx < cnt) {
                float s = 0.f;
#pragma unroll
                for (int j = 0; j < 16; j++)
                    s += Cs[(m * 16 + j) * AST + n] * Xs[j * AST + n];
                const int b = lst[idx];
                const int col = (m == 0) ? c : (128 + c * 3 + (m - 1));
                out[b * OUTW + col] = s;
            }
        }
    }
}

// ---------------------------------------------------------------------------
extern "C" void kernel_launch(void* const* d_in, const int* in_sizes, int n_in,
                              void* d_out, int out_size)
{
    (void)in_sizes; (void)n_in; (void)out_size;
    const float* x    = (const float*)d_in[0];
    const float* y    = (const float*)d_in[1];
    const float* U3_0 = (const float*)d_in[2];
    const float* U2_0 = (const float*)d_in[3];
    const float* U1_0 = (const float*)d_in[4];
    const float* W3_0 = (const float*)d_in[5];
    const float* W2_0 = (const float*)d_in[6];
    const float* W1_0 = (const float*)d_in[7];
    const float* U3_1 = (const float*)d_in[8];
    const float* U2_1 = (const float*)d_in[9];
    const float* U1_1 = (const float*)d_in[10];
    const float* W3_1 = (const float*)d_in[11];
    const float* W2_1 = (const float*)d_in[12];
    const float* W1_1 = (const float*)d_in[13];

    const int smem_main = SMW * (int)sizeof(uint32_t);  // 188,928 B
    cudaFuncSetAttribute(k_main, cudaFuncAttributeMaxDynamicSharedMemorySize, smem_main);

    k_zero<<<1, 32>>>();
    k_group<<<(B_N + 255) / 256, 256>>>(y);
    k_prep2<<<KPRE, 256>>>(U3_0, U2_0, U1_0, W3_0, W2_0, W1_0,
                           U3_1, U2_1, U1_1, W3_1, W2_1, W1_1);
    k_main<<<dim3(C_N, E_N), 256, smem_main>>>(x, (float*)d_out);
}

// round 9
// speedup vs baseline: 5.9088x; 2.7307x over previous
#include <cuda_runtime.h>
#include <cstdint>

// Problem constants
#define B_N   2048
#define C_N   128
#define E_N   10
#define KPN   80       // k-pair rows (160 k values, 10 k16 steps)
#define AST   72       // float stride for Xs / Cs
#define OUTW  512

// Folded, symmetrized, split-bf16 A:
// word[((ec*80 + kp)*64 + mj)*2 + sel], sel0 = bf16x2(hi of krow 2kp, 2kp+1),
// sel1 = bf16x2(lo residuals). ~52.4 MB.
__device__ __align__(16) uint32_t g_A[(size_t)E_N * C_N * KPN * 64 * 2];
__device__ int g_cnt[E_N];
__device__ int g_list[E_N * B_N];

// ---------------------------------------------------------------------------
__global__ void k_zero() {
    if (threadIdx.x < E_N) g_cnt[threadIdx.x] = 0;
}

__global__ void k_group(const float* __restrict__ y) {
    int b = blockIdx.x * blockDim.x + threadIdx.x;
    if (b >= B_N) return;
    int e = 0;
#pragma unroll
    for (int q = 0; q < E_N; q++)
        if (y[b * E_N + q] > 0.5f) e = q;
    int pos = atomicAdd(&g_cnt[e], 1);
    g_list[e * B_N + pos] = b;
}

// ---------------------------------------------------------------------------
// bf16 split: hi = truncate-to-bf16, lo = rn-bf16 of residual; pack 2 krows.
__device__ __forceinline__ void split_pack(float v0, float v1,
                                           uint32_t& hiw, uint32_t& low) {
    uint32_t u0 = __float_as_uint(v0), u1 = __float_as_uint(v1);
    hiw = __byte_perm(u0, u1, 0x7632);
    float l0 = v0 - __uint_as_float(u0 & 0xffff0000u);
    float l1 = v1 - __uint_as_float(u1 & 0xffff0000u);
    asm("cvt.rn.bf16x2.f32 %0, %1, %2;" : "=r"(low) : "f"(l1), "f"(l0));
}

// Triangular row r (0..135) -> (l, i), l <= i, order (0,0),(0,1)..(0,15),(1,1)..
__device__ __forceinline__ void tri_li(int r, int& l, int& i) {
    l = 0;
    int rr = r;
    while (rr >= 16 - l) { rr -= 16 - l; l++; }
    i = l + rr;
}

// ---------------------------------------------------------------------------
// k_prep3: one block per (kp, ec-fifth). Computes both krows r=2kp,2kp+1 for
// 256 ec's, f32x2-packed FFMA, splits to bf16 hi/lo, coalesced uint2 stores.
template <int K0, int K1>
__device__ void prep_compute(int kp, int jb,
                             const float* __restrict__ W0,
                             const float* __restrict__ W1,
                             const float* __restrict__ us0,
                             const float* __restrict__ us1,
                             float* __restrict__ Os, int tid)
{
    const int ec_l = tid & 31;
    const int slot = tid >> 5;
    const int h    = slot >> 2;     // krow half
    const int mjg  = slot & 3;      // 0: irrep0 (mj 0..15), 1..3: irrep1

    for (int ch8 = 0; ch8 < 8; ch8++) {
        const int ec = (jb * 8 + ch8) * 32 + ec_l;
        const int e = ec >> 7, c = ec & 127;
        unsigned long long acc[8];
#pragma unroll
        for (int q = 0; q < 8; q++) acc[q] = 0ull;

        if (mjg == 0) {
            const unsigned long long* u64 =
                (const unsigned long long*)(us0 + h * 384);
#pragma unroll
            for (int k = 0; k < K0; k++) {
                float wk = W0[(e * K0 + k) * 128 + c];
                unsigned long long wp;
                asm("mov.b64 %0, {%1,%1};" : "=l"(wp) : "f"(wk));
#pragma unroll
                for (int q = 0; q < 8; q++) {
                    unsigned long long u = u64[k * 8 + q];
                    asm("fma.rn.f32x2 %0, %1, %2, %0;"
                        : "+l"(acc[q]) : "l"(u), "l"(wp));
                }
            }
        } else {
            const int mb = (mjg - 1) * 16;
            const unsigned long long* u64 =
                (const unsigned long long*)(us1 + h * 1632 + mb);
#pragma unroll
            for (int k = 0; k < K1; k++) {
                float wk = W1[(e * K1 + k) * 128 + c];
                unsigned long long wp;
                asm("mov.b64 %0, {%1,%1};" : "=l"(wp) : "f"(wk));
#pragma unroll
                for (int q = 0; q < 8; q++) {
                    unsigned long long u = u64[k * 24 + q];
                    asm("fma.rn.f32x2 %0, %1, %2, %0;"
                        : "+l"(acc[q]) : "l"(u), "l"(wp));
                }
            }
        }
#pragma unroll
        for (int q = 0; q < 8; q++) {
            float o0, o1;
            asm("mov.b64 {%0,%1}, %2;" : "=f"(o0), "=f"(o1) : "l"(acc[q]));
            Os[ec_l * 130 + h * 64 + mjg * 16 + 2 * q]     = o0;
            Os[ec_l * 130 + h * 64 + mjg * 16 + 2 * q + 1] = o1;
        }
        __syncthreads();

        for (int widx = tid; widx < 2048; widx += 256) {
            int el = widx >> 6, mj = widx & 63;
            float o0 = Os[el * 130 + mj];
            float o1 = Os[el * 130 + 64 + mj];
            uint32_t hiw, low;
            split_pack(o0, o1, hiw, low);
            size_t gi = (((size_t)((jb * 8 + ch8) * 32 + el) * KPN + kp) * 64 + mj) * 2;
            *(uint2*)&g_A[gi] = make_uint2(hiw, low);
        }
        __syncthreads();
    }
}

__global__ void __launch_bounds__(256) k_prep3(
    const float* __restrict__ U3_0, const float* __restrict__ U2_0, const float* __restrict__ U1_0,
    const float* __restrict__ W3_0, const float* __restrict__ W2_0, const float* __restrict__ W1_0,
    const float* __restrict__ U3_1, const float* __restrict__ U2_1, const float* __restrict__ U1_1,
    const float* __restrict__ W3_1, const float* __restrict__ W2_1, const float* __restrict__ W1_1)
{
    __shared__ __align__(16) float us0[768];     // [2][K0<=24][16 j]
    __shared__ __align__(16) float us1[3264];    // [2][K1<=34][48 mj]
    __shared__ float Os[32 * 130];

    const int kp = blockIdx.x, jb = blockIdx.y;
    const int tid = threadIdx.x;

    if (kp <= 67) {
        // both halves triangular: fold (l,i) + (i,l) for l<i
        for (int h = 0; h < 2; h++) {
            int r = 2 * kp + h, l, i;
            tri_li(r, l, i);
            for (int idx = tid; idx < 23 * 16; idx += 256) {
                int k = idx >> 4, j = idx & 15;
                float v = U3_0[((i * 16 + j) * 16 + l) * 23 + k];
                if (l < i) v += U3_0[((l * 16 + j) * 16 + i) * 23 + k];
                us0[h * 384 + k * 16 + j] = v;
            }
            for (int idx = tid; idx < 33 * 48; idx += 256) {
                int k = idx / 48, mj = idx % 48, m = mj >> 4, j = mj & 15;
                float v = U3_1[(((m * 16 + i) * 16 + j) * 16 + l) * 33 + k];
                if (l < i) v += U3_1[(((m * 16 + l) * 16 + j) * 16 + i) * 33 + k];
                us1[h * 1632 + k * 48 + mj] = v;
            }
        }
        __syncthreads();
        prep_compute<23, 33>(kp, jb, W3_0, W3_1, us0, us1, Os, tid);
    } else if (kp <= 75) {
        // linear x rows: krow r=136+j0 -> U2 with l=j0
        for (int h = 0; h < 2; h++) {
            int j0 = 2 * kp + h - 136;
            for (int idx = tid; idx < 4 * 16; idx += 256) {
                int k = idx >> 4, j = idx & 15;
                us0[h * 384 + k * 16 + j] = U2_0[(j * 16 + j0) * 4 + k];
            }
            for (int idx = tid; idx < 5 * 48; idx += 256) {
                int k = idx / 48, mj = idx % 48, m = mj >> 4, j = mj & 15;
                us1[h * 1632 + k * 48 + mj] = U2_1[((m * 16 + j) * 16 + j0) * 5 + k];
            }
        }
        __syncthreads();
        prep_compute<4, 5>(kp, jb, W2_0, W2_1, us0, us1, Os, tid);
    } else {
        // kp 76: h0 = const row (U1), h1 = zero. kp 77..79: zeros.
        for (int idx = tid; idx < 768; idx += 256) us0[idx] = 0.f;
        for (int idx = tid; idx < 3264; idx += 256) us1[idx] = 0.f;
        __syncthreads();
        if (kp == 76) {
            if (tid < 16) us0[tid] = U1_0[tid];
            if (tid < 48) us1[tid] = U1_1[tid];
        }
        __syncthreads();
        prep_compute<1, 1>(kp, jb, W1_0, W1_1, us0, us1, Os, tid);
    }
}

// ---------------------------------------------------------------------------
__device__ __forceinline__ void mma_bf16(float* d,
                                         uint32_t a0, uint32_t a1, uint32_t a2, uint32_t a3,
                                         uint32_t b0, uint32_t b1) {
    asm volatile(
        "mma.sync.aligned.m16n8k16.row.col.f32.bf16.bf16.f32 "
        "{%0,%1,%2,%3}, {%4,%5,%6,%7}, {%8,%9}, {%0,%1,%2,%3};"
        : "+f"(d[0]), "+f"(d[1]), "+f"(d[2]), "+f"(d[3])
        : "r"(a0), "r"(a1), "r"(a2), "r"(a3), "r"(b0), "r"(b1));
}

// smem word offsets for k_main (uint32 units)
#define SM_A   0                       // 80 * 128 = 10240
#define SM_B   10240                   // 10240
#define SM_X   20480                   // 18 * 72 floats = 1296
#define SM_C   21776                   // 64 * 72 floats = 4608
#define SM_LUT 26384                   // 160 words
#define SM_WORDS 26544                 // 106,176 B -> 2 CTAs/SM

// k_main: per (c, e) CTA, 256 threads / 8 warps, 2 CTAs/SM.
// out4[64 x 64] = A[64 x 160] * B[160 x 64], split-bf16 (hh+hl+lh).
// A/B smem: word addr = kp*128 + ((col + 4*(kp&3)) & 63)*2 + sel (hi/lo).
__global__ void __launch_bounds__(256, 2) k_main(const float* __restrict__ x,
                                                 float* __restrict__ out)
{
    extern __shared__ uint32_t sm[];
    uint32_t* Aw  = sm + SM_A;
    uint32_t* Bw  = sm + SM_B;
    float*    Xs  = (float*)(sm + SM_X);   // rows 0..15 = x, 16 = valid, 17 = 0
    float*    Cs  = (float*)(sm + SM_C);
    uint32_t* lut = sm + SM_LUT;           // (pl | pi<<16) per krow

    const int c = blockIdx.x, e = blockIdx.y;
    const int tid  = threadIdx.x;
    const int lane = tid & 31, warp = tid >> 5;
    const int gid  = lane >> 2, tig = lane & 3;
    const int m_base = (warp & 3) * 16;
    const int n_base = (warp >> 2) * 32;

    // --- one-time init: LUT, zero row, A tile load (swizzled) ---
    if (tid < 160) {
        int pl, pi;
        if (tid < 136)      { int l, i; tri_li(tid, l, i); pl = l; pi = i; }
        else if (tid < 152) { pl = tid - 136; pi = 16; }
        else if (tid == 152){ pl = 16; pi = 16; }
        else                { pl = 17; pi = 17; }
        lut[tid] = (uint32_t)pl | ((uint32_t)pi << 16);
    }
    if (tid < AST) Xs[17 * AST + tid] = 0.f;
    {
        const uint4* srcA = (const uint4*)&g_A[(size_t)(e * C_N + c) * (KPN * 128)];
        for (int idx = tid; idx < KPN * 32; idx += 256) {
            int kp = idx >> 5, mp = idx & 31;          // mj pair index
            int mjp = (mp * 2 + 4 * (kp & 3)) & 63;    // rotated (stays even)
            *(uint4*)&Aw[kp * 128 + mjp * 2] = srcA[idx];
        }
    }

    const int cnt = g_cnt[e];
    const int* lst = &g_list[e * B_N];
    const int ntiles = (cnt + 63) >> 6;

    const int n   = tid & 63;
    const int grp = tid >> 6;     // 4 groups x 20 kp rows

    for (int t = 0; t < ntiles; t++) {
        __syncthreads();   // init / previous tile fully consumed

        // --- phase 0: grp 0 fills Xs ---
        if (grp == 0) {
            const int idx = t * 64 + n;
            float4 v0, v1, v2, v3;
            float vld;
            if (idx < cnt) {
                const float4* xp = (const float4*)&x[((size_t)lst[idx] * C_N + c) * 16];
                v0 = xp[0]; v1 = xp[1]; v2 = xp[2]; v3 = xp[3];
                vld = 1.f;
            } else {
                v0 = v1 = v2 = v3 = make_float4(0.f, 0.f, 0.f, 0.f);
                vld = 0.f;
            }
            Xs[0*AST+n]=v0.x;  Xs[1*AST+n]=v0.y;  Xs[2*AST+n]=v0.z;  Xs[3*AST+n]=v0.w;
            Xs[4*AST+n]=v1.x;  Xs[5*AST+n]=v1.y;  Xs[6*AST+n]=v1.z;  Xs[7*AST+n]=v1.w;
            Xs[8*AST+n]=v2.x;  Xs[9*AST+n]=v2.y;  Xs[10*AST+n]=v2.z; Xs[11*AST+n]=v2.w;
            Xs[12*AST+n]=v3.x; Xs[13*AST+n]=v3.y; Xs[14*AST+n]=v3.z; Xs[15*AST+n]=v3.w;
            Xs[16*AST+n]=vld;
        }
        __syncthreads();

        // --- phase 1: build split B (20 kp rows per thread) ---
#pragma unroll 5
        for (int s = 0; s < 20; s++) {
            const int kp = grp * 20 + s;
            const uint32_t lu0 = lut[2 * kp], lu1 = lut[2 * kp + 1];
            float v0 = Xs[(lu0 & 0xffff) * AST + n] * Xs[(lu0 >> 16) * AST + n];
            float v1 = Xs[(lu1 & 0xffff) * AST + n] * Xs[(lu1 >> 16) * AST + n];
            uint32_t hiw, low;
            split_pack(v0, v1, hiw, low);
            *(uint2*)&Bw[kp * 128 + (((n + 4 * (kp & 3)) & 63) * 2)] =
                make_uint2(hiw, low);
        }
        __syncthreads();

        // --- tensor GEMM: 10 k16-steps, hh + hl + lh ---
        float d[4][4];
#pragma unroll
        for (int nf = 0; nf < 4; nf++)
#pragma unroll
            for (int q = 0; q < 4; q++) d[nf][q] = 0.f;

        const int mjA0 = ((m_base + gid + 4 * tig) & 63) * 2;
        const int mjA1 = ((m_base + 8 + gid + 4 * tig) & 63) * 2;
#pragma unroll
        for (int ks = 0; ks < 10; ks++) {
            const int r0 = (ks * 8 + tig) * 128;
            const int r1 = (ks * 8 + 4 + tig) * 128;
            uint2 a0p = *(uint2*)&Aw[r0 + mjA0];
            uint2 a1p = *(uint2*)&Aw[r0 + mjA1];
            uint2 a2p = *(uint2*)&Aw[r1 + mjA0];
            uint2 a3p = *(uint2*)&Aw[r1 + mjA1];
#pragma unroll
            for (int nf = 0; nf < 4; nf++) {
                const int nn = ((n_base + nf * 8 + gid + 4 * tig) & 63) * 2;
                uint2 b0p = *(uint2*)&Bw[r0 + nn];
                uint2 b1p = *(uint2*)&Bw[r1 + nn];
                mma_bf16(d[nf], a0p.x, a1p.x, a2p.x, a3p.x, b0p.x, b1p.x);  // hh
                mma_bf16(d[nf], a0p.x, a1p.x, a2p.x, a3p.x, b0p.y, b1p.y);  // hl
                mma_bf16(d[nf], a0p.y, a1p.y, a2p.y, a3p.y, b0p.x, b1p.x);  // lh
            }
        }

        // --- stash C ---
#pragma unroll
        for (int nf = 0; nf < 4; nf++) {
            const int nn = n_base + nf * 8 + 2 * tig;
            *(float2*)&Cs[(m_base + gid) * AST + nn]     = make_float2(d[nf][0], d[nf][1]);
            *(float2*)&Cs[(m_base + 8 + gid) * AST + nn] = make_float2(d[nf][2], d[nf][3]);
        }
        __syncthreads();

        // --- epilogue: out[m,n] = sum_j C[m*16+j,n] * x_j[n] ---
        {
            const int m = tid >> 6;
            const int idx = t * 64 + n;
            if (idx < cnt) {
                float s = 0.f;
#pragma unroll
                for (int j = 0; j < 16; j++)
                    s += Cs[(m * 16 + j) * AST + n] * Xs[j * AST + n];
                const int b = lst[idx];
                const int col = (m == 0) ? c : (128 + c * 3 + (m - 1));
                out[b * OUTW + col] = s;
            }
        }
    }
}

// ---------------------------------------------------------------------------
extern "C" void kernel_launch(void* const* d_in, const int* in_sizes, int n_in,
                              void* d_out, int out_size)
{
    (void)in_sizes; (void)n_in; (void)out_size;
    const float* x    = (const float*)d_in[0];
    const float* y    = (const float*)d_in[1];
    const float* U3_0 = (const float*)d_in[2];
    const float* U2_0 = (const float*)d_in[3];
    const float* U1_0 = (const float*)d_in[4];
    const float* W3_0 = (const float*)d_in[5];
    const float* W2_0 = (const float*)d_in[6];
    const float* W1_0 = (const float*)d_in[7];
    const float* U3_1 = (const float*)d_in[8];
    const float* U2_1 = (const float*)d_in[9];
    const float* U1_1 = (const float*)d_in[10];
    const float* W3_1 = (const float*)d_in[11];
    const float* W2_1 = (const float*)d_in[12];
    const float* W1_1 = (const float*)d_in[13];

    const int smem_main = SM_WORDS * (int)sizeof(uint32_t);  // 106,176 B
    cudaFuncSetAttribute(k_main, cudaFuncAttributeMaxDynamicSharedMemorySize, smem_main);

    k_zero<<<1, 32>>>();
    k_group<<<(B_N + 255) / 256, 256>>>(y);
    k_prep3<<<dim3(KPN, 5), 256>>>(U3_0, U2_0, U1_0, W3_0, W2_0, W1_0,
                                   U3_1, U2_1, U1_1, W3_1, W2_1, W1_1);
    k_main<<<dim3(C_N, E_N), 256, smem_main>>>(x, (float*)d_out);
}